// round 9
// baseline (speedup 1.0000x reference)
#include <cuda_runtime.h>
#include <cuda_fp16.h>

// LBP uniform (P=8, R=1) over (B,C,H,W)=(32,3,512,512) float32.
// R9: MIO-op attack. Evidence: R4/R7/R8 all plateau ~41us at issue~71%;
// 20 MIO ops per 256px (incl 6 single-lane halo LDGs + 6 SHFL) ~ LSU-issue
// floor ~26us. Changes:
//  (a) one warp = one full 512-px row (16px/lane): NO halo loads at all
//      (image borders are zero), 22 MIO ops per 512px (0.043/px, was 0.078).
//  (b) rows held as f16x2 (cvt.rz: exact compares vs integer centers since
//      v>=k <=> RZ(v)>=k for v>=0, and floor(RZ(v))=floor(v)); compares via
//      __hge2 (1.0/0.0 per half) + __hfma2 weight chain = 2 px per op on the
//      underused FMA pipe.

#define IMG_W 512
#define IMG_H 512

__device__ __forceinline__ unsigned prmt(unsigned a, unsigned b, unsigned sel) {
    unsigned d;
    asm("prmt.b32 %0, %1, %2, %3;" : "=r"(d) : "r"(a), "r"(b), "r"(sel));
    return d;
}

// pack two floats into f16x2 with round-toward-zero (hi goes to upper half)
__device__ __forceinline__ unsigned pack_rz(float hi, float lo) {
    unsigned d;
    asm("cvt.rz.f16x2.f32 %0, %1, %2;" : "=r"(d) : "f"(hi), "f"(lo));
    return d;
}

__device__ __forceinline__ __half2 u2h(unsigned x) {
    __half2 h;
    *reinterpret_cast<unsigned*>(&h) = x;
    return h;
}

// convert one 16-px row slice (4 float4) to 8 f16x2 regs, scaled by 255
__device__ __forceinline__ void conv_row(const float* p, bool valid, unsigned q[8]) {
    if (valid) {
        const float4 v0 = *reinterpret_cast<const float4*>(p);
        const float4 v1 = *reinterpret_cast<const float4*>(p + 4);
        const float4 v2 = *reinterpret_cast<const float4*>(p + 8);
        const float4 v3 = *reinterpret_cast<const float4*>(p + 12);
        q[0] = pack_rz(v0.y * 255.f, v0.x * 255.f);
        q[1] = pack_rz(v0.w * 255.f, v0.z * 255.f);
        q[2] = pack_rz(v1.y * 255.f, v1.x * 255.f);
        q[3] = pack_rz(v1.w * 255.f, v1.z * 255.f);
        q[4] = pack_rz(v2.y * 255.f, v2.x * 255.f);
        q[5] = pack_rz(v2.w * 255.f, v2.z * 255.f);
        q[6] = pack_rz(v3.y * 255.f, v3.x * 255.f);
        q[7] = pack_rz(v3.w * 255.f, v3.z * 255.f);
    } else {
#pragma unroll
        for (int i = 0; i < 8; i++) q[i] = 0u;
    }
}

__global__ __launch_bounds__(256)
void lbp_kernel(const float* __restrict__ x, float* __restrict__ out, int nrows) {
    const int r    = blockIdx.x * (blockDim.x >> 5) + (threadIdx.x >> 5);
    const int lane = threadIdx.x & 31;
    if (r >= nrows) return;

    const int h = r & (IMG_H - 1);
    const bool hasTop = (h != 0);
    const bool hasBot = (h != IMG_H - 1);

    const float* rowc = x + (size_t)r * IMG_W + lane * 16;

    unsigned t[8], c[8], b[8];
    conv_row(rowc - IMG_W, hasTop, t);
    conv_row(rowc,         true,   c);
    conv_row(rowc + IMG_W, hasBot, b);

    // cross-lane halos: left needs hi-half of lane-1's reg7; right needs
    // lo-half of lane+1's reg0. Image borders (lane 0 left / lane 31 right)=0.
    unsigned tup = __shfl_up_sync(0xFFFFFFFFu, t[7], 1);
    unsigned cup = __shfl_up_sync(0xFFFFFFFFu, c[7], 1);
    unsigned bup = __shfl_up_sync(0xFFFFFFFFu, b[7], 1);
    unsigned tdn = __shfl_down_sync(0xFFFFFFFFu, t[0], 1);
    unsigned cdn = __shfl_down_sync(0xFFFFFFFFu, c[0], 1);
    unsigned bdn = __shfl_down_sync(0xFFFFFFFFu, b[0], 1);
    if (lane == 0)  { tup = 0u; cup = 0u; bup = 0u; }
    if (lane == 31) { tdn = 0u; cdn = 0u; bdn = 0u; }

    const __half2 W2   = u2h(0x40004000u);
    const __half2 W4   = u2h(0x44004400u);
    const __half2 W8   = u2h(0x48004800u);
    const __half2 W16  = u2h(0x4C004C00u);
    const __half2 W32  = u2h(0x50005000u);
    const __half2 W64  = u2h(0x54005400u);
    const __half2 W128 = u2h(0x58005800u);

    float res[16];
#pragma unroll
    for (int i = 0; i < 8; i++) {
        const unsigned tprev = i ? t[i - 1] : tup;
        const unsigned cprev = i ? c[i - 1] : cup;
        const unsigned bprev = i ? b[i - 1] : bup;
        const unsigned tnext = (i < 7) ? t[i + 1] : tdn;
        const unsigned cnext = (i < 7) ? c[i + 1] : cdn;
        const unsigned bnext = (i < 7) ? b[i + 1] : bdn;
        // shifted pixel-pair windows (lo=px-1,hi=px) and (lo=px+1,hi=px+2)
        const unsigned tm1 = prmt(tprev, t[i], 0x5432u);
        const unsigned tp1 = prmt(t[i], tnext, 0x5432u);
        const unsigned cm1 = prmt(cprev, c[i], 0x5432u);
        const unsigned cp1 = prmt(c[i], cnext, 0x5432u);
        const unsigned bm1 = prmt(bprev, b[i], 0x5432u);
        const unsigned bp1 = prmt(b[i], bnext, 0x5432u);

        const __half2 fc = h2floor(u2h(c[i]));  // exact integer centers
        // circular order bits 0..7: tl, t, tr, r, br, b, bl, l
        __half2 m2;
        m2 = __hge2(u2h(tm1),  fc);
        m2 = __hfma2(__hge2(u2h(t[i]), fc), W2,   m2);
        m2 = __hfma2(__hge2(u2h(tp1),  fc), W4,   m2);
        m2 = __hfma2(__hge2(u2h(cp1),  fc), W8,   m2);
        m2 = __hfma2(__hge2(u2h(bp1),  fc), W16,  m2);
        m2 = __hfma2(__hge2(u2h(b[i]), fc), W32,  m2);
        m2 = __hfma2(__hge2(u2h(bm1),  fc), W64,  m2);
        m2 = __hfma2(__hge2(u2h(cm1),  fc), W128, m2);

        const unsigned mlo = (unsigned)__half2int_rz(__low2half(m2));
        const unsigned mhi = (unsigned)__half2int_rz(__high2half(m2));
#pragma unroll
        for (int k = 0; k < 2; k++) {
            const unsigned m   = k ? mhi : mlo;
            const unsigned mm  = m * 0x101u;          // m | m<<8
            const unsigned rot = (mm >> 7) & 0xFFu;   // circular rot-left-1
            const int trans = __popc(m ^ rot);
            const int ones  = __popc(m);
            const int lbp   = (trans <= 2) ? ones : 9;
            res[2 * i + k] = (float)lbp * (1.0f / 255.0f);
        }
    }

    float* op = out + (size_t)r * IMG_W + lane * 16;
#pragma unroll
    for (int k = 0; k < 4; k++)
        *reinterpret_cast<float4*>(op + 4 * k) =
            make_float4(res[4 * k], res[4 * k + 1], res[4 * k + 2], res[4 * k + 3]);
}

extern "C" void kernel_launch(void* const* d_in, const int* in_sizes, int n_in,
                              void* d_out, int out_size) {
    const float* x = (const float*)d_in[0];
    float* out = (float*)d_out;
    const int nrows = out_size / IMG_W;    // B*C*H = 49152
    const int threads = 256;               // 8 warps/block, 1 row/warp
    const int blocks = (nrows + 7) / 8;
    lbp_kernel<<<blocks, threads>>>(x, out, nrows);
}

// round 10
// speedup vs baseline: 1.1149x; 1.1149x over previous
#include <cuda_runtime.h>
#include <cuda_fp16.h>

// LBP uniform (P=8, R=1) over (B,C,H,W)=(32,3,512,512) float32.
// R10 = R9's exact f16x2 compare/fma math + fully-coalesced layout.
// One warp = one 512-px row; lane L owns px {4L+128k : k=0..3} (4 chunks of
// 4 px). Every float4 LDG/STG is perfectly coalesced (512B/warp request).
// No halo loads: chunk-edge halos via circular shfl with sender-side select.
// f16x2 exactness: RZ(255x) compares vs integer centers identically to f32
// (k<=255 exact in f16; RZ never crosses an integer boundary).

#define IMG_W 512
#define IMG_H 512

__device__ __forceinline__ unsigned prmt(unsigned a, unsigned b, unsigned sel) {
    unsigned d;
    asm("prmt.b32 %0, %1, %2, %3;" : "=r"(d) : "r"(a), "r"(b), "r"(sel));
    return d;
}

// pack two floats into f16x2 with round-toward-zero (hi arg -> upper half)
__device__ __forceinline__ unsigned pack_rz(float hi, float lo) {
    unsigned d;
    asm("cvt.rz.f16x2.f32 %0, %1, %2;" : "=r"(d) : "f"(hi), "f"(lo));
    return d;
}

__device__ __forceinline__ __half2 u2h(unsigned x) {
    __half2 h;
    *reinterpret_cast<unsigned*>(&h) = x;
    return h;
}

__global__ __launch_bounds__(256)
void lbp_kernel(const float* __restrict__ x, float* __restrict__ out, int nrows) {
    const int r    = blockIdx.x * (blockDim.x >> 5) + (threadIdx.x >> 5);
    const int lane = threadIdx.x & 31;
    if (r >= nrows) return;

    const int h = r & (IMG_H - 1);
    const bool hasTop = (h != 0);
    const bool hasBot = (h != IMG_H - 1);

    const float* rowc = x + (size_t)r * IMG_W + lane * 4;

    // q[row][k][p]: row 0=t,1=c,2=b; chunk k; pair p (p0=px0,1 p1=px2,3)
    unsigned t[4][2], c[4][2], b[4][2];
#pragma unroll
    for (int k = 0; k < 4; k++) {
        const int off = 128 * k;
        {   // center row always valid
            const float4 v = *reinterpret_cast<const float4*>(rowc + off);
            c[k][0] = pack_rz(v.y * 255.f, v.x * 255.f);
            c[k][1] = pack_rz(v.w * 255.f, v.z * 255.f);
        }
        if (hasTop) {
            const float4 v = *reinterpret_cast<const float4*>(rowc - IMG_W + off);
            t[k][0] = pack_rz(v.y * 255.f, v.x * 255.f);
            t[k][1] = pack_rz(v.w * 255.f, v.z * 255.f);
        } else { t[k][0] = 0u; t[k][1] = 0u; }
        if (hasBot) {
            const float4 v = *reinterpret_cast<const float4*>(rowc + IMG_W + off);
            b[k][0] = pack_rz(v.y * 255.f, v.x * 255.f);
            b[k][1] = pack_rz(v.w * 255.f, v.z * 255.f);
        } else { b[k][0] = 0u; b[k][1] = 0u; }
    }

    // halo regs: al[k].hi = px(4L+128k-1), ar[k].lo = px(4L+128k+4)
    unsigned tal[4], tar[4], cal[4], car[4], bal[4], bar[4];
    const int upLane = (lane + 31) & 31;   // circular: lane0 reads lane31
    const int dnLane = (lane + 1) & 31;    // circular: lane31 reads lane0
#pragma unroll
    for (int k = 0; k < 4; k++) {
        // sender-side select: lane31 serves receiver lane0 with prev chunk;
        // lane0 serves receiver lane31 with next chunk. borders -> 0.
        unsigned ls, rs;
        ls = (lane == 31) ? (k > 0 ? t[k - 1][1] : 0u) : t[k][1];
        tal[k] = __shfl_sync(0xFFFFFFFFu, ls, upLane);
        rs = (lane == 0) ? (k < 3 ? t[k + 1][0] : 0u) : t[k][0];
        tar[k] = __shfl_sync(0xFFFFFFFFu, rs, dnLane);
        ls = (lane == 31) ? (k > 0 ? c[k - 1][1] : 0u) : c[k][1];
        cal[k] = __shfl_sync(0xFFFFFFFFu, ls, upLane);
        rs = (lane == 0) ? (k < 3 ? c[k + 1][0] : 0u) : c[k][0];
        car[k] = __shfl_sync(0xFFFFFFFFu, rs, dnLane);
        ls = (lane == 31) ? (k > 0 ? b[k - 1][1] : 0u) : b[k][1];
        bal[k] = __shfl_sync(0xFFFFFFFFu, ls, upLane);
        rs = (lane == 0) ? (k < 3 ? b[k + 1][0] : 0u) : b[k][0];
        bar[k] = __shfl_sync(0xFFFFFFFFu, rs, dnLane);
    }

    const __half2 W2   = u2h(0x40004000u);
    const __half2 W4   = u2h(0x44004400u);
    const __half2 W8   = u2h(0x48004800u);
    const __half2 W16  = u2h(0x4C004C00u);
    const __half2 W32  = u2h(0x50005000u);
    const __half2 W64  = u2h(0x54005400u);
    const __half2 W128 = u2h(0x58005800u);

    float* op = out + (size_t)r * IMG_W + lane * 4;
#pragma unroll
    for (int k = 0; k < 4; k++) {
        // shifted windows: xm=(px-1,px0) xmid=(px1,px2) xp=(px3,px4)
        const unsigned tm = prmt(tal[k], t[k][0], 0x5432u);
        const unsigned tmid = prmt(t[k][0], t[k][1], 0x5432u);
        const unsigned tp = prmt(t[k][1], tar[k], 0x5432u);
        const unsigned cm = prmt(cal[k], c[k][0], 0x5432u);
        const unsigned cmid = prmt(c[k][0], c[k][1], 0x5432u);
        const unsigned cp = prmt(c[k][1], car[k], 0x5432u);
        const unsigned bm = prmt(bal[k], b[k][0], 0x5432u);
        const unsigned bmid = prmt(b[k][0], b[k][1], 0x5432u);
        const unsigned bp = prmt(b[k][1], bar[k], 0x5432u);

        float res[4];
#pragma unroll
        for (int p = 0; p < 2; p++) {
            const __half2 fc = h2floor(u2h(c[k][p]));  // exact int centers
            const unsigned ntl = p ? tmid : tm;
            const unsigned ntr = p ? tp   : tmid;
            const unsigned ncl = p ? cmid : cm;
            const unsigned ncr = p ? cp   : cmid;
            const unsigned nbl = p ? bmid : bm;
            const unsigned nbr = p ? bp   : bmid;
            // circular order bits 0..7: tl, t, tr, r, br, b, bl, l
            __half2 m2;
            m2 = __hge2(u2h(ntl), fc);
            m2 = __hfma2(__hge2(u2h(t[k][p]), fc), W2,   m2);
            m2 = __hfma2(__hge2(u2h(ntr),     fc), W4,   m2);
            m2 = __hfma2(__hge2(u2h(ncr),     fc), W8,   m2);
            m2 = __hfma2(__hge2(u2h(nbr),     fc), W16,  m2);
            m2 = __hfma2(__hge2(u2h(b[k][p]), fc), W32,  m2);
            m2 = __hfma2(__hge2(u2h(nbl),     fc), W64,  m2);
            m2 = __hfma2(__hge2(u2h(ncl),     fc), W128, m2);

            const unsigned mlo = (unsigned)__half2int_rz(__low2half(m2));
            const unsigned mhi = (unsigned)__half2int_rz(__high2half(m2));
#pragma unroll
            for (int q = 0; q < 2; q++) {
                const unsigned m   = q ? mhi : mlo;
                const unsigned mm  = m * 0x101u;          // m | m<<8
                const unsigned rot = (mm >> 7) & 0xFFu;   // rot-left-1
                const int trans = __popc(m ^ rot);
                const int ones  = __popc(m);
                const int lbp   = (trans <= 2) ? ones : 9;
                res[2 * p + q] = (float)lbp * (1.0f / 255.0f);
            }
        }
        *reinterpret_cast<float4*>(op + 128 * k) =
            make_float4(res[0], res[1], res[2], res[3]);
    }
}

extern "C" void kernel_launch(void* const* d_in, const int* in_sizes, int n_in,
                              void* d_out, int out_size) {
    const float* x = (const float*)d_in[0];
    float* out = (float*)d_out;
    const int nrows = out_size / IMG_W;    // B*C*H = 49152
    const int threads = 256;               // 8 warps/block, 1 row/warp
    const int blocks = (nrows + 7) / 8;
    lbp_kernel<<<blocks, threads>>>(x, out, nrows);
}

// round 11
// speedup vs baseline: 1.3775x; 1.2355x over previous
#include <cuda_runtime.h>
#include <cuda_fp16.h>

// LBP uniform (P=8, R=1) over (B,C,H,W)=(32,3,512,512) float32.
// R11 = R10 (coalesced interleaved chunks + exact f16x2 math) restructured as
// a software-pipelined chunk loop with 1-chunk lookahead:
//  - MLP_p1 drops 12 -> ~3 (kills cross-CTA L1tex-queue contention / CTA spread)
//  - loads/shuffles/compute/store interleaved -> scheduler always has work
//  - live regs ~halved (cur+next chunk only) -> occupancy up
// Layout: one warp = one 512-px row; lane L owns px {4L+128k}, k=0..3.

#define IMG_W 512
#define IMG_H 512
#define FULL 0xFFFFFFFFu

__device__ __forceinline__ unsigned prmt(unsigned a, unsigned b, unsigned sel) {
    unsigned d;
    asm("prmt.b32 %0, %1, %2, %3;" : "=r"(d) : "r"(a), "r"(b), "r"(sel));
    return d;
}

// pack two floats into f16x2 with round-toward-zero (hi arg -> upper half)
__device__ __forceinline__ unsigned pack_rz(float hi, float lo) {
    unsigned d;
    asm("cvt.rz.f16x2.f32 %0, %1, %2;" : "=r"(d) : "f"(hi), "f"(lo));
    return d;
}

__device__ __forceinline__ __half2 u2h(unsigned x) {
    __half2 h;
    *reinterpret_cast<unsigned*>(&h) = x;
    return h;
}

// load+convert one chunk (4 px) of the 3 rows
__device__ __forceinline__ void load_chunk(const float* rowc, int off,
                                           bool hasTop, bool hasBot,
                                           unsigned& T0, unsigned& T1,
                                           unsigned& C0, unsigned& C1,
                                           unsigned& B0, unsigned& B1) {
    const float4 v = *reinterpret_cast<const float4*>(rowc + off);
    C0 = pack_rz(v.y * 255.f, v.x * 255.f);
    C1 = pack_rz(v.w * 255.f, v.z * 255.f);
    if (hasTop) {
        const float4 w = *reinterpret_cast<const float4*>(rowc - IMG_W + off);
        T0 = pack_rz(w.y * 255.f, w.x * 255.f);
        T1 = pack_rz(w.w * 255.f, w.z * 255.f);
    } else { T0 = 0u; T1 = 0u; }
    if (hasBot) {
        const float4 w = *reinterpret_cast<const float4*>(rowc + IMG_W + off);
        B0 = pack_rz(w.y * 255.f, w.x * 255.f);
        B1 = pack_rz(w.w * 255.f, w.z * 255.f);
    } else { B0 = 0u; B1 = 0u; }
}

__global__ __launch_bounds__(256, 6)
void lbp_kernel(const float* __restrict__ x, float* __restrict__ out, int nrows) {
    const int r    = blockIdx.x * (blockDim.x >> 5) + (threadIdx.x >> 5);
    const int lane = threadIdx.x & 31;
    if (r >= nrows) return;

    const int h = r & (IMG_H - 1);
    const bool hasTop = (h != 0);
    const bool hasBot = (h != IMG_H - 1);

    const float* rowc = x + (size_t)r * IMG_W + lane * 4;
    float* op = out + (size_t)r * IMG_W + lane * 4;

    const int upLane = (lane + 31) & 31;   // circular: lane0 <- lane31
    const int dnLane = (lane + 1) & 31;    // circular: lane31 <- lane0

    const __half2 W2   = u2h(0x40004000u);
    const __half2 W4   = u2h(0x44004400u);
    const __half2 W8   = u2h(0x48004800u);
    const __half2 W16  = u2h(0x4C004C00u);
    const __half2 W32  = u2h(0x50005000u);
    const __half2 W64  = u2h(0x54005400u);
    const __half2 W128 = u2h(0x58005800u);

    // prev-chunk edge words (word[1]); 0 for k==0 (left image border)
    unsigned pt1 = 0u, pc1 = 0u, pb1 = 0u;
    // current chunk
    unsigned t0, t1, c0, c1, b0, b1;
    load_chunk(rowc, 0, hasTop, hasBot, t0, t1, c0, c1, b0, b1);

#pragma unroll
    for (int k = 0; k < 4; k++) {
        // lookahead: next chunk (zeros past right image border)
        unsigned nt0 = 0u, nt1 = 0u, nc0 = 0u, nc1 = 0u, nb0 = 0u, nb1 = 0u;
        if (k < 3)
            load_chunk(rowc, 128 * (k + 1), hasTop, hasBot,
                       nt0, nt1, nc0, nc1, nb0, nb1);

        // halos via circular shfl + sender-side select:
        //  left : receiver L gets word[1] of lane L-1 (lane0 <- lane31's PREV chunk)
        //  right: receiver L gets word[0] of lane L+1 (lane31 <- lane0's NEXT chunk)
        unsigned ls, rs;
        ls = (lane == 31) ? pt1 : t1;  const unsigned tal = __shfl_sync(FULL, ls, upLane);
        rs = (lane == 0)  ? nt0 : t0;  const unsigned tar = __shfl_sync(FULL, rs, dnLane);
        ls = (lane == 31) ? pc1 : c1;  const unsigned cal = __shfl_sync(FULL, ls, upLane);
        rs = (lane == 0)  ? nc0 : c0;  const unsigned car = __shfl_sync(FULL, rs, dnLane);
        ls = (lane == 31) ? pb1 : b1;  const unsigned bal = __shfl_sync(FULL, ls, upLane);
        rs = (lane == 0)  ? nb0 : b0;  const unsigned bar = __shfl_sync(FULL, rs, dnLane);

        // shifted pixel-pair windows: m=(px-1,px0) mid=(px1,px2) p=(px3,px4)
        const unsigned tm   = prmt(tal, t0, 0x5432u);
        const unsigned tmid = prmt(t0,  t1, 0x5432u);
        const unsigned tp   = prmt(t1, tar, 0x5432u);
        const unsigned cm   = prmt(cal, c0, 0x5432u);
        const unsigned cmid = prmt(c0,  c1, 0x5432u);
        const unsigned cp   = prmt(c1, car, 0x5432u);
        const unsigned bm   = prmt(bal, b0, 0x5432u);
        const unsigned bmid = prmt(b0,  b1, 0x5432u);
        const unsigned bp   = prmt(b1, bar, 0x5432u);

        float res[4];
#pragma unroll
        for (int p = 0; p < 2; p++) {
            const __half2 fc = h2floor(u2h(p ? c1 : c0));  // exact int centers
            const unsigned ntl = p ? tmid : tm;
            const unsigned ntr = p ? tp   : tmid;
            const unsigned ncl = p ? cmid : cm;
            const unsigned ncr = p ? cp   : cmid;
            const unsigned nbl = p ? bmid : bm;
            const unsigned nbr = p ? bp   : bmid;
            const unsigned tc  = p ? t1 : t0;
            const unsigned bc  = p ? b1 : b0;
            // circular order bits 0..7: tl, t, tr, r, br, b, bl, l
            __half2 m2;
            m2 = __hge2(u2h(ntl), fc);
            m2 = __hfma2(__hge2(u2h(tc),  fc), W2,   m2);
            m2 = __hfma2(__hge2(u2h(ntr), fc), W4,   m2);
            m2 = __hfma2(__hge2(u2h(ncr), fc), W8,   m2);
            m2 = __hfma2(__hge2(u2h(nbr), fc), W16,  m2);
            m2 = __hfma2(__hge2(u2h(bc),  fc), W32,  m2);
            m2 = __hfma2(__hge2(u2h(nbl), fc), W64,  m2);
            m2 = __hfma2(__hge2(u2h(ncl), fc), W128, m2);

            const unsigned mlo = (unsigned)__half2int_rz(__low2half(m2));
            const unsigned mhi = (unsigned)__half2int_rz(__high2half(m2));
#pragma unroll
            for (int q = 0; q < 2; q++) {
                const unsigned m   = q ? mhi : mlo;
                const unsigned mm  = m * 0x101u;          // m | m<<8
                const unsigned rot = (mm >> 7) & 0xFFu;   // rot-left-1
                const int trans = __popc(m ^ rot);
                const int ones  = __popc(m);
                const int lbp   = (trans <= 2) ? ones : 9;
                res[2 * p + q] = (float)lbp * (1.0f / 255.0f);
            }
        }
        *reinterpret_cast<float4*>(op + 128 * k) =
            make_float4(res[0], res[1], res[2], res[3]);

        // rotate pipeline state
        pt1 = t1; pc1 = c1; pb1 = b1;
        t0 = nt0; t1 = nt1; c0 = nc0; c1 = nc1; b0 = nb0; b1 = nb1;
    }
}

extern "C" void kernel_launch(void* const* d_in, const int* in_sizes, int n_in,
                              void* d_out, int out_size) {
    const float* x = (const float*)d_in[0];
    float* out = (float*)d_out;
    const int nrows = out_size / IMG_W;    // B*C*H = 49152
    const int threads = 256;               // 8 warps/block, 1 row/warp
    const int blocks = (nrows + 7) / 8;
    lbp_kernel<<<blocks, threads>>>(x, out, nrows);
}

// round 12
// speedup vs baseline: 1.5918x; 1.1556x over previous
#include <cuda_runtime.h>
#include <cuda_fp16.h>

// LBP uniform (P=8, R=1) over (B,C,H,W)=(32,3,512,512) float32.
// R12 = R11 (pipelined coalesced chunks + exact f16x2 compares) extended to
// TWO output rows per warp (4 input rows loaded instead of 6 per 2 rows) and
// mul.rn.f32x2 packed scaling feeding cvt.rz.f16x2 (2 ops per 2 px convert).
// Two independent compare chains per chunk double ILP inside the serial
// hge2->hfma2 dependency chain.

#define IMG_W 512
#define IMG_H 512
#define FULL 0xFFFFFFFFu

__device__ __forceinline__ unsigned prmt(unsigned a, unsigned b, unsigned sel) {
    unsigned d;
    asm("prmt.b32 %0, %1, %2, %3;" : "=r"(d) : "r"(a), "r"(b), "r"(sel));
    return d;
}

// two packed floats (lo,hi) * 255 -> f16x2 (RZ). Exact: RN f32 mul then RZ.
__device__ __forceinline__ unsigned conv2(unsigned long long px2) {
    unsigned d;
    asm("{\n\t"
        ".reg .b64 t;\n\t"
        ".reg .f32 lo, hi;\n\t"
        "mul.rn.f32x2 t, %1, %2;\n\t"
        "mov.b64 {lo, hi}, t;\n\t"
        "cvt.rz.f16x2.f32 %0, hi, lo;\n\t"
        "}"
        : "=r"(d) : "l"(px2), "l"(0x437F0000437F0000ull));  // 255.0f x2
    return d;
}

__device__ __forceinline__ __half2 u2h(unsigned x) {
    __half2 h;
    *reinterpret_cast<unsigned*>(&h) = x;
    return h;
}

// load one chunk (4 px) of one row and convert to two f16x2 words
__device__ __forceinline__ void load4(const float* p, unsigned& w0, unsigned& w1) {
    const ulonglong2 u = *reinterpret_cast<const ulonglong2*>(p);
    w0 = conv2(u.x);
    w1 = conv2(u.y);
}

__global__ __launch_bounds__(256, 5)
void lbp_kernel(const float* __restrict__ x, float* __restrict__ out, int npairs) {
    const int pr   = blockIdx.x * (blockDim.x >> 5) + (threadIdx.x >> 5);
    const int lane = threadIdx.x & 31;
    if (pr >= npairs) return;

    const int r0 = pr * 2;                 // even; pair stays inside one image
    const int h0 = r0 & (IMG_H - 1);
    const bool hasTop = (h0 != 0);
    const bool hasBot = (h0 != IMG_H - 2);

    const float* rb = x + (size_t)r0 * IMG_W + lane * 4;   // row r0
    const float* ra = rb - IMG_W;                           // row r0-1
    const float* rc = rb + IMG_W;                           // row r0+1
    const float* rd = rb + 2 * IMG_W;                       // row r0+2
    float* op0 = out + (size_t)r0 * IMG_W + lane * 4;
    float* op1 = op0 + IMG_W;

    const int upLane = (lane + 31) & 31;
    const int dnLane = (lane + 1) & 31;

    const __half2 W2   = u2h(0x40004000u);
    const __half2 W4   = u2h(0x44004400u);
    const __half2 W8   = u2h(0x48004800u);
    const __half2 W16  = u2h(0x4C004C00u);
    const __half2 W32  = u2h(0x50005000u);
    const __half2 W64  = u2h(0x54005400u);
    const __half2 W128 = u2h(0x58005800u);

    // prev-chunk edge words (word[1]) per row; 0 at left image border
    unsigned pa1 = 0u, pb1 = 0u, pc1 = 0u, pd1 = 0u;
    // current chunk: rows a (top), b (=r0), c (=r1), d (bottom)
    unsigned a0, a1, b0, b1, c0, c1, d0, d1;
    if (hasTop) load4(ra, a0, a1); else { a0 = 0u; a1 = 0u; }
    load4(rb, b0, b1);
    load4(rc, c0, c1);
    if (hasBot) load4(rd, d0, d1); else { d0 = 0u; d1 = 0u; }

#pragma unroll
    for (int k = 0; k < 4; k++) {
        // lookahead: next chunk
        unsigned na0 = 0u, na1 = 0u, nb0 = 0u, nb1 = 0u;
        unsigned nc0 = 0u, nc1 = 0u, nd0 = 0u, nd1 = 0u;
        if (k < 3) {
            const int off = 128 * (k + 1);
            if (hasTop) load4(ra + off, na0, na1);
            load4(rb + off, nb0, nb1);
            load4(rc + off, nc0, nc1);
            if (hasBot) load4(rd + off, nd0, nd1);
        }

        // halos: left = word1 of lane-1 (lane0 <- lane31's prev chunk);
        //        right = word0 of lane+1 (lane31 <- lane0's next chunk)
        unsigned ls, rs;
        ls = (lane == 31) ? pa1 : a1;  const unsigned aal = __shfl_sync(FULL, ls, upLane);
        rs = (lane == 0)  ? na0 : a0;  const unsigned aar = __shfl_sync(FULL, rs, dnLane);
        ls = (lane == 31) ? pb1 : b1;  const unsigned bal = __shfl_sync(FULL, ls, upLane);
        rs = (lane == 0)  ? nb0 : b0;  const unsigned bar = __shfl_sync(FULL, rs, dnLane);
        ls = (lane == 31) ? pc1 : c1;  const unsigned cal = __shfl_sync(FULL, ls, upLane);
        rs = (lane == 0)  ? nc0 : c0;  const unsigned car = __shfl_sync(FULL, rs, dnLane);
        ls = (lane == 31) ? pd1 : d1;  const unsigned dal = __shfl_sync(FULL, ls, upLane);
        rs = (lane == 0)  ? nd0 : d0;  const unsigned dar = __shfl_sync(FULL, rs, dnLane);

        // shifted windows per row: m=(px-1,px0) mid=(px1,px2) p=(px3,px4)
        const unsigned am = prmt(aal, a0, 0x5432u), amid = prmt(a0, a1, 0x5432u), ap = prmt(a1, aar, 0x5432u);
        const unsigned bm = prmt(bal, b0, 0x5432u), bmid = prmt(b0, b1, 0x5432u), bp = prmt(b1, bar, 0x5432u);
        const unsigned cm = prmt(cal, c0, 0x5432u), cmid = prmt(c0, c1, 0x5432u), cp = prmt(c1, car, 0x5432u);
        const unsigned dm = prmt(dal, d0, 0x5432u), dmid = prmt(d0, d1, 0x5432u), dp = prmt(d1, dar, 0x5432u);

        float res0[4], res1[4];
#pragma unroll
        for (int p = 0; p < 2; p++) {
            // output row 0: top=a, center=b, bottom=c
            const __half2 fc0 = h2floor(u2h(p ? b1 : b0));
            // output row 1: top=b, center=c, bottom=d
            const __half2 fc1 = h2floor(u2h(p ? c1 : c0));

            const unsigned tl0 = p ? amid : am, tc0 = p ? a1 : a0, tr0 = p ? ap : amid;
            const unsigned cl0 = p ? bmid : bm, cr0 = p ? bp : bmid;
            const unsigned bl0 = p ? cmid : cm, bc0 = p ? c1 : c0, br0 = p ? cp : cmid;

            const unsigned tl1 = p ? bmid : bm, tc1 = p ? b1 : b0, tr1 = p ? bp : bmid;
            const unsigned cl1 = p ? cmid : cm, cr1 = p ? cp : cmid;
            const unsigned bl1 = p ? dmid : dm, bc1 = p ? d1 : d0, br1 = p ? dp : dmid;

            // two independent weighted chains (circular order: tl,t,tr,r,br,b,bl,l)
            __half2 m0, m1;
            m0 = __hge2(u2h(tl0), fc0);
            m1 = __hge2(u2h(tl1), fc1);
            m0 = __hfma2(__hge2(u2h(tc0), fc0), W2,   m0);
            m1 = __hfma2(__hge2(u2h(tc1), fc1), W2,   m1);
            m0 = __hfma2(__hge2(u2h(tr0), fc0), W4,   m0);
            m1 = __hfma2(__hge2(u2h(tr1), fc1), W4,   m1);
            m0 = __hfma2(__hge2(u2h(cr0), fc0), W8,   m0);
            m1 = __hfma2(__hge2(u2h(cr1), fc1), W8,   m1);
            m0 = __hfma2(__hge2(u2h(br0), fc0), W16,  m0);
            m1 = __hfma2(__hge2(u2h(br1), fc1), W16,  m1);
            m0 = __hfma2(__hge2(u2h(bc0), fc0), W32,  m0);
            m1 = __hfma2(__hge2(u2h(bc1), fc1), W32,  m1);
            m0 = __hfma2(__hge2(u2h(bl0), fc0), W64,  m0);
            m1 = __hfma2(__hge2(u2h(bl1), fc1), W64,  m1);
            m0 = __hfma2(__hge2(u2h(cl0), fc0), W128, m0);
            m1 = __hfma2(__hge2(u2h(cl1), fc1), W128, m1);

            const unsigned m0lo = (unsigned)__half2int_rz(__low2half(m0));
            const unsigned m0hi = (unsigned)__half2int_rz(__high2half(m0));
            const unsigned m1lo = (unsigned)__half2int_rz(__low2half(m1));
            const unsigned m1hi = (unsigned)__half2int_rz(__high2half(m1));
#pragma unroll
            for (int q = 0; q < 2; q++) {
                {
                    const unsigned m   = q ? m0hi : m0lo;
                    const unsigned mm  = m * 0x101u;
                    const unsigned rot = (mm >> 7) & 0xFFu;
                    const int trans = __popc(m ^ rot);
                    const int ones  = __popc(m);
                    res0[2 * p + q] = (float)((trans <= 2) ? ones : 9) * (1.0f / 255.0f);
                }
                {
                    const unsigned m   = q ? m1hi : m1lo;
                    const unsigned mm  = m * 0x101u;
                    const unsigned rot = (mm >> 7) & 0xFFu;
                    const int trans = __popc(m ^ rot);
                    const int ones  = __popc(m);
                    res1[2 * p + q] = (float)((trans <= 2) ? ones : 9) * (1.0f / 255.0f);
                }
            }
        }
        *reinterpret_cast<float4*>(op0 + 128 * k) = make_float4(res0[0], res0[1], res0[2], res0[3]);
        *reinterpret_cast<float4*>(op1 + 128 * k) = make_float4(res1[0], res1[1], res1[2], res1[3]);

        // rotate pipeline state
        pa1 = a1; pb1 = b1; pc1 = c1; pd1 = d1;
        a0 = na0; a1 = na1; b0 = nb0; b1 = nb1;
        c0 = nc0; c1 = nc1; d0 = nd0; d1 = nd1;
    }
}

extern "C" void kernel_launch(void* const* d_in, const int* in_sizes, int n_in,
                              void* d_out, int out_size) {
    const float* x = (const float*)d_in[0];
    float* out = (float*)d_out;
    const int nrows  = out_size / IMG_W;   // B*C*H = 49152
    const int npairs = nrows / 2;          // 24576 warps, 1 row-pair/warp
    const int threads = 256;               // 8 warps/block
    const int blocks = (npairs + 7) / 8;
    lbp_kernel<<<blocks, threads>>>(x, out, npairs);
}